// round 2
// baseline (speedup 1.0000x reference)
#include <cuda_runtime.h>
#include <cstdint>
#include <cstddef>

// Problem constants
#define B_   16
#define NPT  4096      // points in set 1 (per batch)
#define SPT  1024      // points in set 2 (per batch)
#define D1_  256
#define D2_  128
#define CIN  384       // D1 + D2
#define CO   256       // output channels of both conv layers
#define NS   (B_*NPT)  // 65536 samples for BN stats

// ---------------------------------------------------------------------------
// Scratch (device globals: allocation-free per harness rules)
// ---------------------------------------------------------------------------
__device__ float g_p2t[B_ * SPT * D2_];          //  8 MB: points2 transposed [B,S,D2]
__device__ float g_interp[B_ * D2_ * NPT];       // 32 MB: interpolated feats [B,D2,N]
__device__ float g_y1[B_ * CO * NPT];            // 64 MB: layer-1 pre-BN output
__device__ float g_alpha1[CO], g_beta1[CO];      // folded BN affine, layer 1
__device__ float g_alpha2[CO], g_beta2[CO];      // folded BN affine, layer 2

// ---------------------------------------------------------------------------
// Kernel 1: transpose points2 [B,D2,S] -> g_p2t [B,S,D2]  (coalesced both ways)
// ---------------------------------------------------------------------------
__global__ void k_transpose(const float* __restrict__ p2)
{
    __shared__ float t[32][33];
    const int b  = blockIdx.z;
    const int c0 = blockIdx.y * 32;
    const int s0 = blockIdx.x * 32;
    const int tx = threadIdx.x, ty = threadIdx.y;
#pragma unroll
    for (int i = 0; i < 4; i++) {
        int c = c0 + ty + i * 8;
        t[ty + i * 8][tx] = p2[((size_t)b * D2_ + c) * SPT + s0 + tx];
    }
    __syncthreads();
#pragma unroll
    for (int i = 0; i < 4; i++) {
        int s = s0 + ty + i * 8;
        g_p2t[((size_t)b * SPT + s) * D2_ + c0 + tx] = t[tx][ty + i * 8];
    }
}

// ---------------------------------------------------------------------------
// Kernel 2: 3-NN search + inverse-distance interpolation.
// One block = one batch x 128 query points. Phase 1: each thread scans all
// 1024 reference points (xyz2 staged in smem) keeping the 3 smallest d^2.
// Phase 2: each warp gathers contiguous 512B rows of g_p2t and accumulates
// the weighted sum into a padded smem tile. Phase 3: coalesced write of
// g_interp in [B,D2,N] layout.
// Dynamic smem: 3072 (xyz2) + 384 (w) + 384 (idx) + 128*129 (acc) floats.
// ---------------------------------------------------------------------------
#define INTERP_SMEM ((3072 + 384 + 384 + 128 * 129) * 4)

__global__ void __launch_bounds__(128) k_interp(const float* __restrict__ xyz1,
                                                const float* __restrict__ xyz2)
{
    extern __shared__ float sm[];
    float* x2s = sm;                       // [3][1024]
    float* wsh = sm + 3072;                // [128][3]
    int*   ish = (int*)(sm + 3072 + 384);  // [128][3]
    float* acc = sm + 3072 + 768;          // [128][129] (padded)

    const int b   = blockIdx.y;
    const int n0  = blockIdx.x * 128;
    const int tid = threadIdx.x;

    for (int i = tid; i < 3072; i += 128) x2s[i] = xyz2[(size_t)b * 3072 + i];
    __syncthreads();

    // ---- phase 1: top-3 nearest neighbors for point n0+tid ----
    {
        const int n = n0 + tid;
        const float px = xyz1[((size_t)b * 3 + 0) * NPT + n];
        const float py = xyz1[((size_t)b * 3 + 1) * NPT + n];
        const float pz = xyz1[((size_t)b * 3 + 2) * NPT + n];
        float d0 = 1e30f, d1 = 1e30f, d2 = 1e30f;
        int   i0 = 0,     i1 = 0,     i2 = 0;
#pragma unroll 4
        for (int s = 0; s < SPT; s++) {
            float dx = x2s[s]        - px;
            float dy = x2s[1024 + s] - py;
            float dz = x2s[2048 + s] - pz;
            float d  = fmaf(dx, dx, fmaf(dy, dy, dz * dz));
            if (d < d2) {
                if (d < d1) {
                    if (d < d0) { d2 = d1; i2 = i1; d1 = d0; i1 = i0; d0 = d; i0 = s; }
                    else        { d2 = d1; i2 = i1; d1 = d;  i1 = s; }
                } else          { d2 = d;  i2 = s; }
            }
        }
        float w0 = 1.f / (sqrtf(d0) + 1e-10f);
        float w1 = 1.f / (sqrtf(d1) + 1e-10f);
        float w2 = 1.f / (sqrtf(d2) + 1e-10f);
        float inv = 1.f / (w0 + w1 + w2);
        wsh[tid * 3 + 0] = w0 * inv; ish[tid * 3 + 0] = i0;
        wsh[tid * 3 + 1] = w1 * inv; ish[tid * 3 + 1] = i1;
        wsh[tid * 3 + 2] = w2 * inv; ish[tid * 3 + 2] = i2;
    }
    __syncthreads();

    // ---- phase 2: gather + weighted accumulate (warp per point, coalesced rows) ----
    {
        const int w = tid >> 5, l = tid & 31;
        const float* p2t = g_p2t + (size_t)b * SPT * D2_;
        for (int it = 0; it < 32; it++) {
            const int nl = w * 32 + it;
            float4 a = make_float4(0.f, 0.f, 0.f, 0.f);
#pragma unroll
            for (int k = 0; k < 3; k++) {
                const float wt = wsh[nl * 3 + k];
                const int   id = ish[nl * 3 + k];
                const float4 v = *reinterpret_cast<const float4*>(p2t + (size_t)id * D2_ + l * 4);
                a.x = fmaf(wt, v.x, a.x); a.y = fmaf(wt, v.y, a.y);
                a.z = fmaf(wt, v.z, a.z); a.w = fmaf(wt, v.w, a.w);
            }
            float* row = acc + nl * 129 + l * 4;
            row[0] = a.x; row[1] = a.y; row[2] = a.z; row[3] = a.w;
        }
    }
    __syncthreads();

    // ---- phase 3: coalesced write in [B,D2,N] layout ----
    float* dst = g_interp + ((size_t)b * D2_) * NPT + n0;
    for (int c = 0; c < D2_; c++)
        dst[(size_t)c * NPT + tid] = acc[tid * 129 + c];
}

// ---------------------------------------------------------------------------
// Kernel 3: SGEMM  y[o,s] = sum_c W[o,c] * x[c,s]  (+ bias in epilogue)
// 128x128 tile, BK=16, 256 threads, 8x8 microtile, double-buffered smem.
// Inner loop uses packed fma.rn.f32x2 (2 fp32 FMA per instruction).
// MODE 1: x = concat(points1, g_interp), C = g_y1
// MODE 2: x = relu(alpha1*g_y1 + beta1) fused at load, C = d_out (raw y2)
// ---------------------------------------------------------------------------
template <int MODE>
__global__ void __launch_bounds__(256) k_gemm(const float* __restrict__ A,
                                              const float* __restrict__ Bsrc,
                                              const float* __restrict__ bias,
                                              float* __restrict__ C, int K)
{
    __shared__ float As[2][16][128];
    __shared__ float Bs[2][16][128];

    const int tid = threadIdx.x;
    const int bb  = blockIdx.x >> 5;          // batch
    const int n0  = (blockIdx.x & 31) << 7;   // sample-tile origin within batch
    const int o0  = blockIdx.y << 7;          // output-channel tile origin
    const int tx  = tid & 15, ty = tid >> 4;

    unsigned long long acc[8][4];
#pragma unroll
    for (int i = 0; i < 8; i++)
#pragma unroll
        for (int j = 0; j < 4; j++) acc[i][j] = 0ULL;

    float4 ra[2], rb[2];

    auto g_load = [&](int k0) {
#pragma unroll
        for (int p = 0; p < 2; p++) {                 // A tile: 128 rows x 16 k
            int v = tid + (p << 8);
            int row = v >> 2, kq = (v & 3) << 2;
            ra[p] = *reinterpret_cast<const float4*>(A + (size_t)(o0 + row) * K + (k0 + kq));
        }
#pragma unroll
        for (int p = 0; p < 2; p++) {                 // B tile: 16 k x 128 samples
            int v = tid + (p << 8);
            int r = v >> 5, col = (v & 31) << 2;
            int c = k0 + r;
            float4 t;
            if (MODE == 1) {
                const float* src = (c < D1_)
                    ? (Bsrc     + ((size_t)bb * D1_ + c)        * NPT)
                    : (g_interp + ((size_t)bb * D2_ + (c - D1_)) * NPT);
                t = *reinterpret_cast<const float4*>(src + n0 + col);
            } else {
                const float* src = Bsrc + ((size_t)bb * CO + c) * NPT;
                t = *reinterpret_cast<const float4*>(src + n0 + col);
                const float al = g_alpha1[c], be = g_beta1[c];
                t.x = fmaxf(fmaf(al, t.x, be), 0.f);
                t.y = fmaxf(fmaf(al, t.y, be), 0.f);
                t.z = fmaxf(fmaf(al, t.z, be), 0.f);
                t.w = fmaxf(fmaf(al, t.w, be), 0.f);
            }
            rb[p] = t;
        }
    };

    auto s_store = [&](int buf) {
#pragma unroll
        for (int p = 0; p < 2; p++) {
            int v = tid + (p << 8);
            int row = v >> 2, kq = (v & 3) << 2;
            As[buf][kq + 0][row] = ra[p].x; As[buf][kq + 1][row] = ra[p].y;
            As[buf][kq + 2][row] = ra[p].z; As[buf][kq + 3][row] = ra[p].w;
        }
#pragma unroll
        for (int p = 0; p < 2; p++) {
            int v = tid + (p << 8);
            int r = v >> 5, col = (v & 31) << 2;
            *reinterpret_cast<float4*>(&Bs[buf][r][col]) = rb[p];
        }
    };

    const int KT = K >> 4;
    g_load(0);
    s_store(0);
    __syncthreads();

#pragma unroll 1
    for (int kt = 0; kt < KT; kt++) {
        const int buf = kt & 1;
        if (kt + 1 < KT) g_load((kt + 1) << 4);
#pragma unroll
        for (int k = 0; k < 16; k++) {
            const float4 a0 = *reinterpret_cast<const float4*>(&As[buf][k][ty << 2]);
            const float4 a1 = *reinterpret_cast<const float4*>(&As[buf][k][64 + (ty << 2)]);
            const ulonglong2 p0 = *reinterpret_cast<const ulonglong2*>(&Bs[buf][k][tx << 2]);
            const ulonglong2 p1 = *reinterpret_cast<const ulonglong2*>(&Bs[buf][k][64 + (tx << 2)]);
            const unsigned long long bv0 = p0.x, bv1 = p0.y, bv2 = p1.x, bv3 = p1.y;
            const float aa[8] = {a0.x, a0.y, a0.z, a0.w, a1.x, a1.y, a1.z, a1.w};
#pragma unroll
            for (int i = 0; i < 8; i++) {
                unsigned long long ap;
                asm("mov.b64 %0, {%1, %1};" : "=l"(ap) : "f"(aa[i]));
                asm("fma.rn.f32x2 %0, %1, %2, %0;" : "+l"(acc[i][0]) : "l"(ap), "l"(bv0));
                asm("fma.rn.f32x2 %0, %1, %2, %0;" : "+l"(acc[i][1]) : "l"(ap), "l"(bv1));
                asm("fma.rn.f32x2 %0, %1, %2, %0;" : "+l"(acc[i][2]) : "l"(ap), "l"(bv2));
                asm("fma.rn.f32x2 %0, %1, %2, %0;" : "+l"(acc[i][3]) : "l"(ap), "l"(bv3));
            }
        }
        if (kt + 1 < KT) { s_store((kt + 1) & 1); __syncthreads(); }
    }

    // ---- epilogue: unpack, add bias, vectorized store ----
#pragma unroll
    for (int i = 0; i < 8; i++) {
        const int o = o0 + ((i < 4) ? (ty << 2) + i : 64 + (ty << 2) + i - 4);
        const float bval = bias[o];
        float* dst = C + ((size_t)bb * CO + o) * NPT + n0;
        float x0, x1, x2, x3;
        asm("mov.b64 {%0, %1}, %2;" : "=f"(x0), "=f"(x1) : "l"(acc[i][0]));
        asm("mov.b64 {%0, %1}, %2;" : "=f"(x2), "=f"(x3) : "l"(acc[i][1]));
        float4 o4 = make_float4(x0 + bval, x1 + bval, x2 + bval, x3 + bval);
        *reinterpret_cast<float4*>(dst + (tx << 2)) = o4;
        asm("mov.b64 {%0, %1}, %2;" : "=f"(x0), "=f"(x1) : "l"(acc[i][2]));
        asm("mov.b64 {%0, %1}, %2;" : "=f"(x2), "=f"(x3) : "l"(acc[i][3]));
        float4 o5 = make_float4(x0 + bval, x1 + bval, x2 + bval, x3 + bval);
        *reinterpret_cast<float4*>(dst + 64 + (tx << 2)) = o5;
    }
}

// ---------------------------------------------------------------------------
// Kernel 4: per-channel BN stats (deterministic tree reduce) -> folded affine
// alpha = gamma * rsqrt(var + eps), beta' = beta - mean * alpha
// ---------------------------------------------------------------------------
__global__ void k_stats(const float* __restrict__ y, const float* __restrict__ gamma,
                        const float* __restrict__ beta, int layer)
{
    __shared__ float sh[256], sh2[256];
    const int c = blockIdx.x, tid = threadIdx.x;
    float s = 0.f, ss = 0.f;
    const float* base = y + (size_t)c * NPT;
    for (int i = tid; i < NS; i += 256) {
        const int b = i >> 12, n = i & 4095;
        const float v = base[(size_t)b * CO * NPT + n];
        s += v;
        ss = fmaf(v, v, ss);
    }
    sh[tid] = s; sh2[tid] = ss;
    __syncthreads();
    for (int off = 128; off > 0; off >>= 1) {
        if (tid < off) { sh[tid] += sh[tid + off]; sh2[tid] += sh2[tid + off]; }
        __syncthreads();
    }
    if (tid == 0) {
        const float mean = sh[0] * (1.f / (float)NS);
        const float var  = sh2[0] * (1.f / (float)NS) - mean * mean;
        const float a    = gamma[c] * rsqrtf(var + 1e-5f);
        const float bp   = beta[c] - mean * a;
        if (layer == 1) { g_alpha1[c] = a; g_beta1[c] = bp; }
        else            { g_alpha2[c] = a; g_beta2[c] = bp; }
    }
}

// ---------------------------------------------------------------------------
// Kernel 5: in-place finalize of d_out: out = relu(alpha2*y2 + beta2)
// ---------------------------------------------------------------------------
__global__ void k_finalize(float4* __restrict__ out)
{
    const int i = blockIdx.x * 256 + threadIdx.x;   // float4 index; 1024 per channel row
    float4 v = out[i];
    const int c = (i >> 10) & 255;
    const float a = g_alpha2[c], b = g_beta2[c];
    v.x = fmaxf(fmaf(a, v.x, b), 0.f);
    v.y = fmaxf(fmaf(a, v.y, b), 0.f);
    v.z = fmaxf(fmaf(a, v.z, b), 0.f);
    v.w = fmaxf(fmaf(a, v.w, b), 0.f);
    out[i] = v;
}

// ---------------------------------------------------------------------------
// Launch
// ---------------------------------------------------------------------------
extern "C" void kernel_launch(void* const* d_in, const int* in_sizes, int n_in,
                              void* d_out, int out_size)
{
    const float* xyz1    = (const float*)d_in[0];
    const float* xyz2    = (const float*)d_in[1];
    const float* points1 = (const float*)d_in[2];
    const float* points2 = (const float*)d_in[3];
    const float* W1      = (const float*)d_in[4];
    const float* b1      = (const float*)d_in[5];
    const float* g1      = (const float*)d_in[6];
    const float* be1     = (const float*)d_in[7];
    const float* W2      = (const float*)d_in[8];
    const float* b2      = (const float*)d_in[9];
    const float* g2      = (const float*)d_in[10];
    const float* be2     = (const float*)d_in[11];
    float* out = (float*)d_out;

    void* sym = nullptr;
    cudaGetSymbolAddress(&sym, g_y1);
    float* y1 = (float*)sym;

    cudaFuncSetAttribute(k_interp, cudaFuncAttributeMaxDynamicSharedMemorySize, INTERP_SMEM);

    k_transpose<<<dim3(32, 4, 16), dim3(32, 8)>>>(points2);
    k_interp<<<dim3(32, 16), 128, INTERP_SMEM>>>(xyz1, xyz2);
    k_gemm<1><<<dim3(512, 2), 256>>>(W1, points1, b1, y1, CIN);
    k_stats<<<256, 256>>>(y1, g1, be1, 1);
    k_gemm<2><<<dim3(512, 2), 256>>>(W2, y1, b2, out, CO);
    k_stats<<<256, 256>>>(out, g2, be2, 2);
    k_finalize<<<16384, 256>>>((float4*)out);
}

// round 4
// speedup vs baseline: 1.0470x; 1.0470x over previous
#include <cuda_runtime.h>
#include <cuda_bf16.h>
#include <cstdint>
#include <cstddef>

#define B_   16
#define NPT  4096
#define SPT  1024
#define D1_  256
#define D2_  128
#define CIN  384
#define CO   256
#define NS   (B_*NPT)   // 65536

// ---------------------------------------------------------------------------
// Scratch
// ---------------------------------------------------------------------------
__device__ float         g_p2t[B_ * SPT * D2_];
__device__ __nv_bfloat16 g_x1h[(size_t)NS * CIN];
__device__ __nv_bfloat16 g_x1l[(size_t)NS * CIN];
__device__ __nv_bfloat16 g_x2h[(size_t)NS * CO];
__device__ __nv_bfloat16 g_x2l[(size_t)NS * CO];
__device__ float         g_y1[(size_t)NS * CO];     // y1, then reused as y2
__device__ __nv_bfloat16 g_w1h[CO * CIN], g_w1l[CO * CIN];
__device__ __nv_bfloat16 g_w2h[CO * CO],  g_w2l[CO * CO];
__device__ float g_psum[256 * 256], g_psq[256 * 256];   // deterministic partials
__device__ float g_a1[CO], g_b1[CO], g_a2[CO], g_b2[CO];

__device__ __forceinline__ uint32_t smem_u32(const void* p) {
    uint32_t a;
    asm("{ .reg .u64 t; cvta.to.shared.u64 t, %1; cvt.u32.u64 %0, t; }" : "=r"(a) : "l"(p));
    return a;
}
__device__ __forceinline__ void split_bf16(float a, uint32_t& h, uint32_t& l) {
    __nv_bfloat16 hb = __float2bfloat16(a);
    __nv_bfloat16 lb = __float2bfloat16(a - __bfloat162float(hb));
    h = (uint32_t)__bfloat16_as_ushort(hb);
    l = (uint32_t)__bfloat16_as_ushort(lb);
}

// ---------------------------------------------------------------------------
// W split: fp32 -> bf16 hi/lo
// ---------------------------------------------------------------------------
__global__ void k_wsplit(const float* __restrict__ W1, const float* __restrict__ W2) {
    const int i = blockIdx.x * 256 + threadIdx.x;   // 640 * 256 = 163840
    uint32_t h, l;
    if (i < CO * CIN) {
        split_bf16(W1[i], h, l);
        g_w1h[i] = __ushort_as_bfloat16((unsigned short)h);
        g_w1l[i] = __ushort_as_bfloat16((unsigned short)l);
    } else {
        const int j = i - CO * CIN;
        split_bf16(W2[j], h, l);
        g_w2h[j] = __ushort_as_bfloat16((unsigned short)h);
        g_w2l[j] = __ushort_as_bfloat16((unsigned short)l);
    }
}

// ---------------------------------------------------------------------------
// transpose points2 [B,D2,S] -> g_p2t [B,S,D2]
// ---------------------------------------------------------------------------
__global__ void k_tp2(const float* __restrict__ p2) {
    __shared__ float t[32][33];
    const int b = blockIdx.z, c0 = blockIdx.y * 32, s0 = blockIdx.x * 32;
    const int tx = threadIdx.x, ty = threadIdx.y;
#pragma unroll
    for (int i = 0; i < 4; i++)
        t[ty + i * 8][tx] = p2[((size_t)b * D2_ + c0 + ty + i * 8) * SPT + s0 + tx];
    __syncthreads();
#pragma unroll
    for (int i = 0; i < 4; i++)
        g_p2t[((size_t)b * SPT + s0 + ty + i * 8) * D2_ + c0 + tx] = t[tx][ty + i * 8];
}

// ---------------------------------------------------------------------------
// transpose+split points1 [B,256,N] -> X1 cols [0,256) (sample-major bf16 hi/lo)
// ---------------------------------------------------------------------------
__global__ void k_tp1(const float* __restrict__ p1) {
    __shared__ float t[32][33];   // [c][n]
    const int b = blockIdx.z, c0 = blockIdx.y * 32, n0 = blockIdx.x * 32;
    const int tx = threadIdx.x, ty = threadIdx.y;
    const int tid = ty * 32 + tx;
#pragma unroll
    for (int i = 0; i < 4; i++)
        t[ty + i * 8][tx] = p1[((size_t)b * D1_ + c0 + ty + i * 8) * NPT + n0 + tx];
    __syncthreads();
#pragma unroll
    for (int w = 0; w < 2; w++) {
        const int v = w * 256 + tid;        // 0..511
        const int n = v >> 4, u = v & 15;   // local sample, col-pair
        uint32_t h0, l0, h1, l1;
        split_bf16(t[2 * u][n], h0, l0);
        split_bf16(t[2 * u + 1][n], h1, l1);
        const size_t a = (size_t)(b * NPT + n0 + n) * CIN + c0 + 2 * u;
        *(uint32_t*)(g_x1h + a) = h0 | (h1 << 16);
        *(uint32_t*)(g_x1l + a) = l0 | (l1 << 16);
    }
}

// ---------------------------------------------------------------------------
// 3-NN + inverse-distance interpolation -> X1 cols [256,384) hi/lo
// ---------------------------------------------------------------------------
#define INTERP_SMEM ((3072 + 384 + 384 + 128 * 129) * 4)

__global__ void __launch_bounds__(128) k_interp(const float* __restrict__ xyz1,
                                                const float* __restrict__ xyz2) {
    extern __shared__ float sm[];
    float* x2s = sm;
    float* wsh = sm + 3072;
    int*   ish = (int*)(sm + 3072 + 384);
    float* acc = sm + 3072 + 768;   // [128][129]

    const int b = blockIdx.y, n0 = blockIdx.x * 128, tid = threadIdx.x;

    for (int i = tid; i < 3072; i += 128) x2s[i] = xyz2[(size_t)b * 3072 + i];
    __syncthreads();

    {
        const int n = n0 + tid;
        const float px = xyz1[((size_t)b * 3 + 0) * NPT + n];
        const float py = xyz1[((size_t)b * 3 + 1) * NPT + n];
        const float pz = xyz1[((size_t)b * 3 + 2) * NPT + n];
        float d0 = 1e30f, d1 = 1e30f, d2 = 1e30f;
        int   i0 = 0, i1 = 0, i2 = 0;
#pragma unroll 4
        for (int s = 0; s < SPT; s++) {
            float dx = x2s[s] - px, dy = x2s[1024 + s] - py, dz = x2s[2048 + s] - pz;
            float d = fmaf(dx, dx, fmaf(dy, dy, dz * dz));
            if (d < d2) {
                if (d < d1) {
                    if (d < d0) { d2 = d1; i2 = i1; d1 = d0; i1 = i0; d0 = d; i0 = s; }
                    else        { d2 = d1; i2 = i1; d1 = d;  i1 = s; }
                } else          { d2 = d;  i2 = s; }
            }
        }
        float w0 = 1.f / (sqrtf(d0) + 1e-10f);
        float w1 = 1.f / (sqrtf(d1) + 1e-10f);
        float w2 = 1.f / (sqrtf(d2) + 1e-10f);
        float inv = 1.f / (w0 + w1 + w2);
        wsh[tid * 3 + 0] = w0 * inv; ish[tid * 3 + 0] = i0;
        wsh[tid * 3 + 1] = w1 * inv; ish[tid * 3 + 1] = i1;
        wsh[tid * 3 + 2] = w2 * inv; ish[tid * 3 + 2] = i2;
    }
    __syncthreads();

    {
        const int w = tid >> 5, l = tid & 31;
        const float* p2t = g_p2t + (size_t)b * SPT * D2_;
        for (int it = 0; it < 32; it++) {
            const int nl = w * 32 + it;
            float4 a = make_float4(0.f, 0.f, 0.f, 0.f);
#pragma unroll
            for (int k = 0; k < 3; k++) {
                const float wt = wsh[nl * 3 + k];
                const int   id = ish[nl * 3 + k];
                const float4 v = *reinterpret_cast<const float4*>(p2t + (size_t)id * D2_ + l * 4);
                a.x = fmaf(wt, v.x, a.x); a.y = fmaf(wt, v.y, a.y);
                a.z = fmaf(wt, v.z, a.z); a.w = fmaf(wt, v.w, a.w);
            }
            float* row = acc + nl * 129 + l * 4;
            row[0] = a.x; row[1] = a.y; row[2] = a.z; row[3] = a.w;
        }
    }
    __syncthreads();

    {
        const size_t nb = (size_t)(b * NPT + n0 + tid) * CIN + D1_;
        uint32_t* oh = (uint32_t*)(g_x1h + nb);
        uint32_t* ol = (uint32_t*)(g_x1l + nb);
        const float* row = acc + tid * 129;
#pragma unroll 8
        for (int c = 0; c < D2_; c += 2) {
            uint32_t h0, l0, h1, l1;
            split_bf16(row[c],     h0, l0);
            split_bf16(row[c + 1], h1, l1);
            oh[c >> 1] = h0 | (h1 << 16);
            ol[c >> 1] = l0 | (l1 << 16);
        }
    }
}

// ---------------------------------------------------------------------------
// Warp-MMA GEMM (mma.sync m16n8k16 bf16, fp32 accum, 3-term hi/lo split)
// C[n,256] = X[n,K] * W[256,K]^T
// CTA: 128 samples x 128 channels; K-chunk 64; double-buffered SW128 smem;
// cp.async pipeline. 8 warps in 4(M) x 2(N); warp tile 32x64.
// smem per buffer: Xh 16K | Xl 16K | Wh 16K | Wl 16K = 64KB; x2 = 128KB.
// ---------------------------------------------------------------------------
#define MMA_SMEM (2 * 65536 + 1024)

template <int LAYER>
__global__ void __launch_bounds__(256) k_mma() {
    constexpr int K  = (LAYER == 1) ? CIN : CO;
    constexpr int KT = K / 64;
    const __nv_bfloat16* xh = (LAYER == 1) ? g_x1h : g_x2h;
    const __nv_bfloat16* xl = (LAYER == 1) ? g_x1l : g_x2l;
    const __nv_bfloat16* wh = (LAYER == 1) ? g_w1h : g_w2h;
    const __nv_bfloat16* wl = (LAYER == 1) ? g_w1l : g_w2l;
    float* C = g_y1;

    extern __shared__ uint8_t dsm[];
    const uint32_t sbase = (smem_u32(dsm) + 1023) & ~1023u;

    const int tid  = threadIdx.x, wid = tid >> 5, lane = tid & 31;
    const int m0   = blockIdx.x << 7;      // sample tile
    const int n0   = blockIdx.y << 7;      // channel tile
    const int wm   = wid & 3, wn = wid >> 2;

    // ---- cp.async staging of one K-chunk (64 cols) into buffer ----
    auto stage = [&](int kt) {
        const int buf = kt & 1;
        const uint32_t base = sbase + buf * 65536;
        const int k0 = kt * 64;
#pragma unroll
        for (int i = 0; i < 16; i++) {
            const int q = tid + i * 256;           // 0..4095
            const int sel = q >> 10;               // 0 Xh, 1 Xl, 2 Wh, 3 Wl
            const int r = (q & 1023) >> 3, c = q & 7;
            const __nv_bfloat16* src;
            if      (sel == 0) src = xh + (size_t)(m0 + r) * K + k0 + c * 8;
            else if (sel == 1) src = xl + (size_t)(m0 + r) * K + k0 + c * 8;
            else if (sel == 2) src = wh + (size_t)(n0 + r) * K + k0 + c * 8;
            else               src = wl + (size_t)(n0 + r) * K + k0 + c * 8;
            const uint32_t dst = base + sel * 16384 + r * 128 + (((uint32_t)(c ^ (r & 7))) << 4);
            asm volatile("cp.async.cg.shared.global [%0], [%1], 16;" :: "r"(dst), "l"(src));
        }
        asm volatile("cp.async.commit_group;");
    };

    // ---- per-lane ldmatrix row precompute ----
    // A (X): sub s in {0,1}: row = wm*32 + s*16 + (lane&7) + ((lane>>3)&1)*8
    int rA[2], cAx = lane >> 4;   // c offset within k16 (0/1)
#pragma unroll
    for (int s = 0; s < 2; s++)
        rA[s] = wm * 32 + s * 16 + (lane & 7) + ((lane >> 3) & 1) * 8;
    // B (W): pair jj in 0..3: row = wn*64 + (jj*2 + (lane>>4))*8 + (lane&7)
    int rB[4], cBx = (lane >> 3) & 1;
#pragma unroll
    for (int jj = 0; jj < 4; jj++)
        rB[jj] = wn * 64 + (jj * 2 + (lane >> 4)) * 8 + (lane & 7);

    float acc[2][8][4];
#pragma unroll
    for (int s = 0; s < 2; s++)
#pragma unroll
        for (int j = 0; j < 8; j++)
#pragma unroll
            for (int v = 0; v < 4; v++) acc[s][j][v] = 0.f;

    stage(0);
#pragma unroll 1
    for (int kt = 0; kt < KT; kt++) {
        if (kt + 1 < KT) { stage(kt + 1); asm volatile("cp.async.wait_group 1;"); }
        else             { asm volatile("cp.async.wait_group 0;"); }
        __syncthreads();
        const uint32_t base = sbase + (kt & 1) * 65536;
        const uint32_t bXh = base, bXl = base + 16384, bWh = base + 32768, bWl = base + 49152;
#pragma unroll
        for (int ks = 0; ks < 4; ks++) {
            uint32_t ah[2][4], al[2][4], bh[4][4], bl[4][4];
#pragma unroll
            for (int s = 0; s < 2; s++) {
                const uint32_t off = rA[s] * 128 + (((uint32_t)((ks * 2 + cAx) ^ (rA[s] & 7))) << 4);
                asm volatile("ldmatrix.sync.aligned.m8n8.x4.shared.b16 {%0,%1,%2,%3}, [%4];"
                    : "=r"(ah[s][0]), "=r"(ah[s][1]), "=r"(ah[s][2]), "=r"(ah[s][3]) : "r"(bXh + off));
                asm volatile("ldmatrix.sync.aligned.m8n8.x4.shared.b16 {%0,%1,%2,%3}, [%4];"
                    : "=r"(al[s][0]), "=r"(al[s][1]), "=r"(al[s][2]), "=r"(al[s][3]) : "r"(bXl + off));
            }
#pragma unroll
            for (int jj = 0; jj < 4; jj++) {
                const uint32_t off = rB[jj] * 128 + (((uint32_t)((ks * 2 + cBx) ^ (rB[jj] & 7))) << 4);
                asm volatile("ldmatrix.sync.aligned.m8n8.x4.shared.b16 {%0,%1,%2,%3}, [%4];"
                    : "=r"(bh[jj][0]), "=r"(bh[jj][1]), "=r"(bh[jj][2]), "=r"(bh[jj][3]) : "r"(bWh + off));
                asm volatile("ldmatrix.sync.aligned.m8n8.x4.shared.b16 {%0,%1,%2,%3}, [%4];"
                    : "=r"(bl[jj][0]), "=r"(bl[jj][1]), "=r"(bl[jj][2]), "=r"(bl[jj][3]) : "r"(bWl + off));
            }
#pragma unroll
            for (int s = 0; s < 2; s++)
#pragma unroll
                for (int j = 0; j < 8; j++) {
                    float* cc = acc[s][j];
                    const uint32_t* fh = &bh[j >> 1][(j & 1) * 2];
                    const uint32_t* fl = &bl[j >> 1][(j & 1) * 2];
#define MMA_(A, Bf) asm volatile( \
    "mma.sync.aligned.m16n8k16.row.col.f32.bf16.bf16.f32 " \
    "{%0,%1,%2,%3}, {%4,%5,%6,%7}, {%8,%9}, {%0,%1,%2,%3};" \
    : "+f"(cc[0]), "+f"(cc[1]), "+f"(cc[2]), "+f"(cc[3]) \
    : "r"((A)[0]), "r"((A)[1]), "r"((A)[2]), "r"((A)[3]), "r"((Bf)[0]), "r"((Bf)[1]))
                    MMA_(ah[s], fh);
                    MMA_(al[s], fh);
                    MMA_(ah[s], fl);
#undef MMA_
                }
        }
        __syncthreads();
    }

    // ---- epilogue: direct fp32 stores to C[n,256] ----
#pragma unroll
    for (int s = 0; s < 2; s++) {
        const int m = m0 + wm * 32 + s * 16 + (lane >> 2);
#pragma unroll
        for (int j = 0; j < 8; j++) {
            const int n = n0 + wn * 64 + j * 8 + (lane & 3) * 2;
            *(float2*)(C + (size_t)m * CO + n)       = make_float2(acc[s][j][0], acc[s][j][1]);
            *(float2*)(C + (size_t)(m + 8) * CO + n) = make_float2(acc[s][j][2], acc[s][j][3]);
        }
    }
}

// ---------------------------------------------------------------------------
// stats: deterministic per-channel partial sums over y [n,256]
// block j covers rows j*256..+255; writes partials to g_psum/g_psq
// ---------------------------------------------------------------------------
__global__ void __launch_bounds__(256) k_stats() {
    __shared__ float4 ss[256], qq[256];
    const int j = blockIdx.x, t = threadIdx.x;
    const int cq = t & 63, rq = t >> 6;
    const float4* y = (const float4*)g_y1;
    float4 s = make_float4(0, 0, 0, 0), q = make_float4(0, 0, 0, 0);
    for (int i = 0; i < 64; i++) {
        const int row = j * 256 + rq * 64 + i;
        const float4 v = y[(size_t)row * 64 + cq];
        s.x += v.x; s.y += v.y; s.z += v.z; s.w += v.w;
        q.x = fmaf(v.x, v.x, q.x); q.y = fmaf(v.y, v.y, q.y);
        q.z = fmaf(v.z, v.z, q.z); q.w = fmaf(v.w, v.w, q.w);
    }
    ss[t] = s; qq[t] = q;
    __syncthreads();
    if (t < 64) {
        float4 a = ss[t], b = ss[t + 64], c = ss[t + 128], d = ss[t + 192];
        float4 e = qq[t], f = qq[t + 64], g = qq[t + 128], h = qq[t + 192];
        const int c0 = t * 4;
        g_psum[(c0 + 0) * 256 + j] = a.x + b.x + c.x + d.x;
        g_psum[(c0 + 1) * 256 + j] = a.y + b.y + c.y + d.y;
        g_psum[(c0 + 2) * 256 + j] = a.z + b.z + c.z + d.z;
        g_psum[(c0 + 3) * 256 + j] = a.w + b.w + c.w + d.w;
        g_psq[(c0 + 0) * 256 + j] = e.x + f.x + g.x + h.x;
        g_psq[(c0 + 1) * 256 + j] = e.y + f.y + g.y + h.y;
        g_psq[(c0 + 2) * 256 + j] = e.z + f.z + g.z + h.z;
        g_psq[(c0 + 3) * 256 + j] = e.w + f.w + g.w + h.w;
    }
}

__global__ void k_fold(const float* __restrict__ gamma, const float* __restrict__ beta,
                       int layer) {
    const int c = threadIdx.x;
    float s = 0.f, q = 0.f;
    for (int j = 0; j < 256; j++) { s += g_psum[c * 256 + j]; q += g_psq[c * 256 + j]; }
    const float mean = s * (1.f / (float)NS);
    const float var  = q * (1.f / (float)NS) - mean * mean;
    const float a = gamma[c] * rsqrtf(var + 1e-5f);
    const float b = beta[c] - mean * a;
    if (layer == 1) { g_a1[c] = a; g_b1[c] = b; }
    else            { g_a2[c] = a; g_b2[c] = b; }
}

// ---------------------------------------------------------------------------
// x2 = split(relu(a1*y1 + b1))  [n,256] bf16 hi/lo
// ---------------------------------------------------------------------------
__global__ void __launch_bounds__(256) k_x2() {
    const size_t i = (size_t)blockIdx.x * 256 + threadIdx.x;
    const size_t row = i >> 6;
    const int cq = (int)(i & 63), c0 = cq * 4;
    float4 v = ((const float4*)g_y1)[row * 64 + cq];
    const float4 a = *(const float4*)&g_a1[c0];
    const float4 b = *(const float4*)&g_b1[c0];
    v.x = fmaxf(fmaf(a.x, v.x, b.x), 0.f);
    v.y = fmaxf(fmaf(a.y, v.y, b.y), 0.f);
    v.z = fmaxf(fmaf(a.z, v.z, b.z), 0.f);
    v.w = fmaxf(fmaf(a.w, v.w, b.w), 0.f);
    uint32_t h0, l0, h1, l1, h2, l2, h3, l3;
    split_bf16(v.x, h0, l0); split_bf16(v.y, h1, l1);
    split_bf16(v.z, h2, l2); split_bf16(v.w, h3, l3);
    const size_t o = row * CO + c0;
    *(uint2*)(g_x2h + o) = make_uint2(h0 | (h1 << 16), h2 | (h3 << 16));
    *(uint2*)(g_x2l + o) = make_uint2(l0 | (l1 << 16), l2 | (l3 << 16));
}

// ---------------------------------------------------------------------------
// finalize: out[b,o,n] = relu(a2*y2[n,o] + b2)  (BN + ReLU + transpose)
// ---------------------------------------------------------------------------
__global__ void k_finalize(float* __restrict__ out) {
    __shared__ float t[32][33];
    const int b = blockIdx.z, o0 = blockIdx.y * 32, n0 = blockIdx.x * 32;
    const int tx = threadIdx.x, ty = threadIdx.y;
    const float a = g_a2[o0 + tx], bb = g_b2[o0 + tx];
#pragma unroll
    for (int i = 0; i < 4; i++) {
        const int n = n0 + ty + i * 8;
        const float v = g_y1[(size_t)(b * NPT + n) * CO + o0 + tx];
        t[tx][ty + i * 8] = fmaxf(fmaf(a, v, bb), 0.f);
    }
    __syncthreads();
#pragma unroll
    for (int i = 0; i < 4; i++)
        out[((size_t)b * CO + o0 + ty + i * 8) * NPT + n0 + tx] = t[ty + i * 8][tx];
}

// ---------------------------------------------------------------------------
// Launch
// ---------------------------------------------------------------------------
extern "C" void kernel_launch(void* const* d_in, const int* in_sizes, int n_in,
                              void* d_out, int out_size) {
    const float* xyz1    = (const float*)d_in[0];
    const float* xyz2    = (const float*)d_in[1];
    const float* points1 = (const float*)d_in[2];
    const float* points2 = (const float*)d_in[3];
    const float* W1      = (const float*)d_in[4];
    const float* g1      = (const float*)d_in[6];
    const float* be1     = (const float*)d_in[7];
    const float* W2      = (const float*)d_in[8];
    const float* g2      = (const float*)d_in[10];
    const float* be2     = (const float*)d_in[11];
    float* out = (float*)d_out;

    cudaFuncSetAttribute(k_interp, cudaFuncAttributeMaxDynamicSharedMemorySize, INTERP_SMEM);
    cudaFuncSetAttribute(k_mma<1>, cudaFuncAttributeMaxDynamicSharedMemorySize, MMA_SMEM);
    cudaFuncSetAttribute(k_mma<2>, cudaFuncAttributeMaxDynamicSharedMemorySize, MMA_SMEM);

    k_wsplit<<<640, 256>>>(W1, W2);
    k_tp2<<<dim3(32, 4, 16), dim3(32, 8)>>>(points2);
    k_tp1<<<dim3(128, 8, 16), dim3(32, 8)>>>(points1);
    k_interp<<<dim3(32, 16), 128, INTERP_SMEM>>>(xyz1, xyz2);
    k_mma<1><<<dim3(512, 2), 256, MMA_SMEM>>>();
    k_stats<<<256, 256>>>();
    k_fold<<<1, 256>>>(g1, be1, 1);
    k_x2<<<16384, 256>>>();
    k_mma<2><<<dim3(512, 2), 256, MMA_SMEM>>>();
    k_stats<<<256, 256>>>();
    k_fold<<<1, 256>>>(g2, be2, 2);
    k_finalize<<<dim3(128, 8, 16), dim3(32, 8)>>>(out);
}